// round 2
// baseline (speedup 1.0000x reference)
#include <cuda_runtime.h>
#include <cuda_fp16.h>
#include <cstdint>
#include <cstddef>

#define DEVINL __device__ __forceinline__

// ---------------- problem constants ----------------
static constexpr int B_DIM = 8192;
static constexpr int H_DIM = 1024;
static constexpr int K_DIM = 2048;          // x(1024) || h_prev(1024)

static constexpr int BM = 128;              // batch rows per CTA
static constexpr int BNG = 32;              // hidden cols per CTA (per gate; x4 gates)
static constexpr int BK = 64;               // K per stage
static constexpr int STAGES = 3;
static constexpr int THREADS = 256;
static constexpr int KITERS = K_DIM / BK;   // 32

// fp16 scratch (device globals: allowed scratch mechanism)
__device__ __half g_xh[(size_t)B_DIM * K_DIM];        // 32 MB
__device__ __half g_w[(size_t)4 * H_DIM * K_DIM];     // 16 MB

// SMEM: per stage A 128x64 fp16 (16KB) + B 128x64 fp16 (16KB)
static constexpr uint32_t STAGE_BYTES = 32768;
static constexpr uint32_t B_OFF = 16384;
static constexpr uint32_t SMEM_BYTES = STAGES * STAGE_BYTES + 1024;

// ---------------- PTX helpers ----------------
DEVINL uint32_t smem_u32(const void* p) {
    uint32_t a;
    asm("{ .reg .u64 t; cvta.to.shared.u64 t, %1; cvt.u32.u64 %0, t; }" : "=r"(a) : "l"(p));
    return a;
}
DEVINL void cp16(uint32_t dst, const void* src) {
    asm volatile("cp.async.cg.shared.global [%0], [%1], 16;" :: "r"(dst), "l"(src));
}
DEVINL void cp_commit() { asm volatile("cp.async.commit_group;" ::: "memory"); }
DEVINL void cp_wait1()  { asm volatile("cp.async.wait_group 1;" ::: "memory"); }
DEVINL void cp_wait0()  { asm volatile("cp.async.wait_group 0;" ::: "memory"); }

DEVINL uint32_t swz(uint32_t off) { return off ^ ((off >> 3) & 0x70); }

DEVINL void ldsm_x4(uint32_t& r0, uint32_t& r1, uint32_t& r2, uint32_t& r3, uint32_t addr) {
    asm volatile("ldmatrix.sync.aligned.m8n8.x4.shared.b16 {%0,%1,%2,%3}, [%4];"
                 : "=r"(r0), "=r"(r1), "=r"(r2), "=r"(r3) : "r"(addr));
}
DEVINL void mma16816(float* d, const uint32_t* a, const uint32_t* b) {
    asm volatile("mma.sync.aligned.m16n8k16.row.col.f32.f16.f16.f32 "
                 "{%0,%1,%2,%3}, {%4,%5,%6,%7}, {%8,%9}, {%0,%1,%2,%3};"
                 : "+f"(d[0]), "+f"(d[1]), "+f"(d[2]), "+f"(d[3])
                 : "r"(a[0]), "r"(a[1]), "r"(a[2]), "r"(a[3]), "r"(b[0]), "r"(b[1]));
}

DEVINL float sigmoidf_(float x) { return 1.0f / (1.0f + __expf(-x)); }
DEVINL float tanhf_(float x) {
    float e = __expf(2.0f * x);
    return 1.0f - 2.0f / (e + 1.0f);
}

// ---------------- conversion: fp32 pair -> fp16 concat rows ----------------
// dst[rows][2048]: cols 0-1023 from a-row, 1024-2047 from b-row
__global__ void __launch_bounds__(256)
cvt_pair_kernel(__half* __restrict__ dst, const float* __restrict__ a,
                const float* __restrict__ b, int rows) {
    int idx = blockIdx.x * blockDim.x + threadIdx.x;   // one float4 each
    int total = rows * (K_DIM / 4);
    if (idx >= total) return;
    int c4  = idx & (K_DIM / 4 - 1);   // 0..511
    int row = idx >> 9;
    const float* src = (c4 < 256) ? (a + (size_t)row * H_DIM + c4 * 4)
                                  : (b + (size_t)row * H_DIM + (c4 - 256) * 4);
    float4 v = *reinterpret_cast<const float4*>(src);
    __half2 h0 = __floats2half2_rn(v.x, v.y);
    __half2 h1 = __floats2half2_rn(v.z, v.w);
    uint2 out;
    out.x = *reinterpret_cast<uint32_t*>(&h0);
    out.y = *reinterpret_cast<uint32_t*>(&h1);
    *reinterpret_cast<uint2*>(dst + (size_t)row * K_DIM + c4 * 4) = out;
}

// ---------------- fused GEMM + LSTM epilogue ----------------
DEVINL void load_stage(uint32_t sbase, int kt, int m0, int n0, int tid) {
    const int kbase = kt * BK;
    // A tile: 128 rows x 64 halves (128B rows, SW128-swizzled) = 1024 16B units
#pragma unroll
    for (int i = 0; i < 4; i++) {
        int u = tid + i * THREADS;
        int r = u >> 3, cu = u & 7;
        cp16(sbase + swz((uint32_t)(r * 128 + cu * 16)),
             g_xh + (size_t)(m0 + r) * K_DIM + kbase + cu * 8);
    }
    // B tile: 128 rows (gate*32 + nl) x 64 halves
#pragma unroll
    for (int i = 0; i < 4; i++) {
        int u = tid + i * THREADS;
        int r = u >> 3, cu = u & 7;
        int gate = r >> 5, nl = r & 31;
        cp16(sbase + B_OFF + swz((uint32_t)(r * 128 + cu * 16)),
             g_w + ((size_t)gate * H_DIM + n0 + nl) * K_DIM + kbase + cu * 8);
    }
}

__global__ void __launch_bounds__(THREADS)
lstm_gemm_kernel(const float* __restrict__ c_prev,
                 const float* __restrict__ bxi, const float* __restrict__ bhi,
                 const float* __restrict__ bxf, const float* __restrict__ bhf,
                 const float* __restrict__ bxc, const float* __restrict__ bhc,
                 const float* __restrict__ bxo, const float* __restrict__ bho,
                 float* __restrict__ outH, float* __restrict__ outC) {
    extern __shared__ char smraw[];
    const uint32_t raw  = smem_u32(smraw);
    const uint32_t base = (raw + 1023u) & ~1023u;

    const int tid  = threadIdx.x;
    const int lane = tid & 31;
    const int wid  = tid >> 5;
    const int wm   = wid >> 2;           // 0..1 : 64-row slice
    const int wn   = wid & 3;            // 0..3 : 8-col slice (per gate)
    const int m0   = blockIdx.x * BM;
    const int n0   = blockIdx.y * BNG;

    float acc[4][4][4];                  // [mtile][gate][reg]
#pragma unroll
    for (int t = 0; t < 4; t++)
#pragma unroll
        for (int g = 0; g < 4; g++)
#pragma unroll
            for (int r = 0; r < 4; r++) acc[t][g][r] = 0.0f;

    // prologue: stages 0,1
    load_stage(base + 0 * STAGE_BYTES, 0, m0, n0, tid);
    cp_commit();
    load_stage(base + 1 * STAGE_BYTES, 1, m0, n0, tid);
    cp_commit();

    // precomputed intra-warp ldmatrix offsets (byte offsets before swz)
    const uint32_t aRowOff = (uint32_t)((wm * 64 + (lane & 15)) * 128 + (lane >> 4) * 16);
    const uint32_t bRowLane = (uint32_t)(wn * 8 + (lane & 7));
    const uint32_t bKOff    = (uint32_t)(((lane >> 3) & 1) * 16);
    const uint32_t bGateSel = (uint32_t)(lane >> 4);   // 0/1 within gate pair

    for (int kt = 0; kt < KITERS; kt++) {
        if (kt == KITERS - 1) cp_wait0(); else cp_wait1();
        __syncthreads();

        const uint32_t sA = base + (uint32_t)(kt % STAGES) * STAGE_BYTES;
        const uint32_t sB = sA + B_OFF;

#pragma unroll
        for (int kk = 0; kk < 4; kk++) {
            uint32_t a[4][4];
#pragma unroll
            for (int t = 0; t < 4; t++) {
                uint32_t addr = sA + swz(aRowOff + (uint32_t)(t * 16 * 128) + (uint32_t)(kk * 32));
                ldsm_x4(a[t][0], a[t][1], a[t][2], a[t][3], addr);
            }
            uint32_t b[4][2];
#pragma unroll
            for (int jp = 0; jp < 2; jp++) {
                uint32_t gate = (uint32_t)jp * 2 + bGateSel;
                uint32_t addr = sB + swz((gate * 32 + bRowLane) * 128 + (uint32_t)(kk * 32) + bKOff);
                ldsm_x4(b[jp * 2][0], b[jp * 2][1], b[jp * 2 + 1][0], b[jp * 2 + 1][1], addr);
            }
#pragma unroll
            for (int t = 0; t < 4; t++)
#pragma unroll
                for (int g = 0; g < 4; g++)
                    mma16816(acc[t][g], a[t], b[g]);
        }

        if (kt + 2 < KITERS) {
            load_stage(base + (uint32_t)((kt + 2) % STAGES) * STAGE_BYTES, kt + 2, m0, n0, tid);
            cp_commit();
        }
    }

    // ---------------- epilogue (register-local gate combine) ----------------
    const int cloc = wn * 8 + 2 * (lane & 3);
    const int c    = n0 + cloc;

    const float bi0 = bxi[c] + bhi[c],     bi1 = bxi[c + 1] + bhi[c + 1];
    const float bf0 = bxf[c] + bhf[c],     bf1 = bxf[c + 1] + bhf[c + 1];
    const float bc0 = bxc[c] + bhc[c],     bc1 = bxc[c + 1] + bhc[c + 1];
    const float bo0 = bxo[c] + bho[c],     bo1 = bxo[c + 1] + bho[c + 1];

#pragma unroll
    for (int t = 0; t < 4; t++) {
        const int r0 = m0 + wm * 64 + t * 16 + (lane >> 2);
#pragma unroll
        for (int h = 0; h < 2; h++) {
            const int row = r0 + 8 * h;
            const float2 cp = *reinterpret_cast<const float2*>(c_prev + (size_t)row * H_DIM + c);

            const float zi0 = acc[t][0][2 * h + 0] + bi0, zi1 = acc[t][0][2 * h + 1] + bi1;
            const float zf0 = acc[t][1][2 * h + 0] + bf0, zf1 = acc[t][1][2 * h + 1] + bf1;
            const float zc0 = acc[t][2][2 * h + 0] + bc0, zc1 = acc[t][2][2 * h + 1] + bc1;
            const float zo0 = acc[t][3][2 * h + 0] + bo0, zo1 = acc[t][3][2 * h + 1] + bo1;

            const float cn0 = sigmoidf_(zf0) * cp.x + sigmoidf_(zi0) * tanhf_(zc0);
            const float cn1 = sigmoidf_(zf1) * cp.y + sigmoidf_(zi1) * tanhf_(zc1);
            const float hn0 = sigmoidf_(zo0) * tanhf_(cn0);
            const float hn1 = sigmoidf_(zo1) * tanhf_(cn1);

            const size_t go = (size_t)row * H_DIM + c;
            *reinterpret_cast<float2*>(outC + go) = make_float2(cn0, cn1);
            *reinterpret_cast<float2*>(outH + go) = make_float2(hn0, hn1);
        }
    }
}

// ---------------- launch ----------------
extern "C" void kernel_launch(void* const* d_in, const int* in_sizes, int n_in,
                              void* d_out, int out_size) {
    (void)in_sizes; (void)n_in; (void)out_size;
    const float* x      = (const float*)d_in[0];
    const float* h_prev = (const float*)d_in[1];
    const float* c_prev = (const float*)d_in[2];
    const float* Wxi = (const float*)d_in[3];
    const float* Whi = (const float*)d_in[4];
    const float* Wxf = (const float*)d_in[5];
    const float* Whf = (const float*)d_in[6];
    const float* Wxc = (const float*)d_in[7];
    const float* Whc = (const float*)d_in[8];
    const float* Wxo = (const float*)d_in[9];
    const float* Who = (const float*)d_in[10];
    const float* bxi = (const float*)d_in[11];
    const float* bhi = (const float*)d_in[12];
    const float* bxf = (const float*)d_in[13];
    const float* bhf = (const float*)d_in[14];
    const float* bxc = (const float*)d_in[15];
    const float* bhc = (const float*)d_in[16];
    const float* bxo = (const float*)d_in[17];
    const float* bho = (const float*)d_in[18];

    float* outH = (float*)d_out;
    float* outC = outH + (size_t)B_DIM * H_DIM;

    __half* xh_p; cudaGetSymbolAddress((void**)&xh_p, g_xh);
    __half* w_p;  cudaGetSymbolAddress((void**)&w_p,  g_w);

    // conversions
    {
        int total = B_DIM * (K_DIM / 4);
        cvt_pair_kernel<<<(total + 255) / 256, 256>>>(xh_p, x, h_prev, B_DIM);
    }
    const float* wx[4] = {Wxi, Wxf, Wxc, Wxo};
    const float* wh[4] = {Whi, Whf, Whc, Who};
    for (int g = 0; g < 4; g++) {
        int total = H_DIM * (K_DIM / 4);
        cvt_pair_kernel<<<(total + 255) / 256, 256>>>(
            w_p + (size_t)g * H_DIM * K_DIM, wx[g], wh[g], H_DIM);
    }

    // fused GEMM + epilogue
    cudaFuncSetAttribute(lstm_gemm_kernel,
                         cudaFuncAttributeMaxDynamicSharedMemorySize, SMEM_BYTES);
    dim3 grid(B_DIM / BM, H_DIM / BNG, 1);   // (64, 32)
    lstm_gemm_kernel<<<grid, THREADS, SMEM_BYTES>>>(
        c_prev, bxi, bhi, bxf, bhf, bxc, bhc, bxo, bho, outH, outC);
}

// round 5
// speedup vs baseline: 1.1595x; 1.1595x over previous
#include <cuda_runtime.h>
#include <cuda_fp16.h>
#include <cstdint>
#include <cstddef>

#define DEVINL __device__ __forceinline__

// ---------------- problem constants ----------------
static constexpr int B_DIM = 8192;
static constexpr int H_DIM = 1024;
static constexpr int K_DIM = 2048;          // x(1024) || h_prev(1024)

static constexpr int BM = 128;              // batch rows per CTA
static constexpr int BNG = 32;              // hidden cols per CTA (per gate; x4 gates)
static constexpr int BK = 64;               // K per stage
static constexpr int STAGES = 3;
static constexpr int THREADS = 256;
static constexpr int KITERS = K_DIM / BK;   // 32
static constexpr int NMBLK = B_DIM / BM;    // 64
static constexpr int NNBLK = H_DIM / BNG;   // 32

// Pre-tiled, pre-swizzled fp16 scratch: each [blk][kt] is a contiguous 16KB
// SMEM-image (128 rows x 64 halves, 128B rows, SW128 swizzled).
static constexpr uint32_t TILE_BYTES = 16384;
__device__ __align__(128) __half g_xh_t[(size_t)NMBLK * KITERS * 8192];  // 32 MB
__device__ __align__(128) __half g_w_t [(size_t)NNBLK * KITERS * 8192];  // 16 MB

// SMEM: per stage A 16KB + B 16KB
static constexpr uint32_t STAGE_BYTES = 32768;
static constexpr uint32_t B_OFF = 16384;
static constexpr uint32_t SMEM_BYTES = STAGES * STAGE_BYTES + 1024;

// ---------------- PTX helpers ----------------
DEVINL uint32_t smem_u32(const void* p) {
    uint32_t a;
    asm("{ .reg .u64 t; cvta.to.shared.u64 t, %1; cvt.u32.u64 %0, t; }" : "=r"(a) : "l"(p));
    return a;
}
DEVINL void cp16(uint32_t dst, const void* src) {
    asm volatile("cp.async.cg.shared.global [%0], [%1], 16;" :: "r"(dst), "l"(src));
}
DEVINL void cp_commit() { asm volatile("cp.async.commit_group;" ::: "memory"); }
DEVINL void cp_wait1()  { asm volatile("cp.async.wait_group 1;" ::: "memory"); }
DEVINL void cp_wait0()  { asm volatile("cp.async.wait_group 0;" ::: "memory"); }

DEVINL uint32_t swz(uint32_t off) { return off ^ ((off >> 3) & 0x70); }

DEVINL void ldsm_x4(uint32_t& r0, uint32_t& r1, uint32_t& r2, uint32_t& r3, uint32_t addr) {
    asm volatile("ldmatrix.sync.aligned.m8n8.x4.shared.b16 {%0,%1,%2,%3}, [%4];"
                 : "=r"(r0), "=r"(r1), "=r"(r2), "=r"(r3) : "r"(addr));
}
DEVINL void mma16816(float* d, const uint32_t* a, const uint32_t* b) {
    asm volatile("mma.sync.aligned.m16n8k16.row.col.f32.f16.f16.f32 "
                 "{%0,%1,%2,%3}, {%4,%5,%6,%7}, {%8,%9}, {%0,%1,%2,%3};"
                 : "+f"(d[0]), "+f"(d[1]), "+f"(d[2]), "+f"(d[3])
                 : "r"(a[0]), "r"(a[1]), "r"(a[2]), "r"(a[3]), "r"(b[0]), "r"(b[1]));
}

DEVINL float sigmoidf_(float x) { return 1.0f / (1.0f + __expf(-x)); }
DEVINL float tanhf_(float x) {
    float e = __expf(2.0f * x);
    return 1.0f - 2.0f / (e + 1.0f);
}

// ---------------- conversion: fp32 -> pre-tiled swizzled fp16 ----------------
// x/h -> g_xh_t. unit = one 16B chunk (8 halves). total 64*32*1024 units.
__global__ void __launch_bounds__(256)
cvt_xh_kernel(const float* __restrict__ x, const float* __restrict__ h) {
    const int u = blockIdx.x * 256 + threadIdx.x;
    const int bu = u >> 10;                // mblk*32 + kt
    const int iu = u & 1023;
    const int r  = iu >> 3, cu = iu & 7;
    const int m  = (bu >> 5) * BM + r;
    const int kt = bu & 31;
    const int k0 = kt * BK + cu * 8;
    const float* src = (k0 < H_DIM) ? (x + (size_t)m * H_DIM + k0)
                                    : (h + (size_t)m * H_DIM + (k0 - H_DIM));
    float4 v0 = *reinterpret_cast<const float4*>(src);
    float4 v1 = *reinterpret_cast<const float4*>(src + 4);
    __half2 h0 = __floats2half2_rn(v0.x, v0.y);
    __half2 h1 = __floats2half2_rn(v0.z, v0.w);
    __half2 h2 = __floats2half2_rn(v1.x, v1.y);
    __half2 h3 = __floats2half2_rn(v1.z, v1.w);
    uint4 out;
    out.x = *reinterpret_cast<uint32_t*>(&h0);
    out.y = *reinterpret_cast<uint32_t*>(&h1);
    out.z = *reinterpret_cast<uint32_t*>(&h2);
    out.w = *reinterpret_cast<uint32_t*>(&h3);
    char* dst = reinterpret_cast<char*>(g_xh_t) + (size_t)bu * TILE_BYTES
              + swz((uint32_t)(r * 128 + cu * 16));
    *reinterpret_cast<uint4*>(dst) = out;
}

// weights -> g_w_t. block rows: gate*32+nl. total 32*32*1024 units.
__global__ void __launch_bounds__(256)
cvt_w_kernel(const float* __restrict__ Wxi, const float* __restrict__ Whi,
             const float* __restrict__ Wxf, const float* __restrict__ Whf,
             const float* __restrict__ Wxc, const float* __restrict__ Whc,
             const float* __restrict__ Wxo, const float* __restrict__ Who) {
    const int u = blockIdx.x * 256 + threadIdx.x;
    const int bu = u >> 10;                // nblk*32 + kt
    const int iu = u & 1023;
    const int rr = iu >> 3, cu = iu & 7;
    const int gate = rr >> 5, nl = rr & 31;
    const int n  = (bu >> 5) * BNG + nl;
    const int kt = bu & 31;
    const int k0 = kt * BK + cu * 8;
    const float* src;
    if (k0 < H_DIM) {
        src = (gate == 0) ? Wxi : (gate == 1) ? Wxf : (gate == 2) ? Wxc : Wxo;
        src += (size_t)n * H_DIM + k0;
    } else {
        src = (gate == 0) ? Whi : (gate == 1) ? Whf : (gate == 2) ? Whc : Who;
        src += (size_t)n * H_DIM + (k0 - H_DIM);
    }
    float4 v0 = *reinterpret_cast<const float4*>(src);
    float4 v1 = *reinterpret_cast<const float4*>(src + 4);
    __half2 h0 = __floats2half2_rn(v0.x, v0.y);
    __half2 h1 = __floats2half2_rn(v0.z, v0.w);
    __half2 h2 = __floats2half2_rn(v1.x, v1.y);
    __half2 h3 = __floats2half2_rn(v1.z, v1.w);
    uint4 out;
    out.x = *reinterpret_cast<uint32_t*>(&h0);
    out.y = *reinterpret_cast<uint32_t*>(&h1);
    out.z = *reinterpret_cast<uint32_t*>(&h2);
    out.w = *reinterpret_cast<uint32_t*>(&h3);
    char* dst = reinterpret_cast<char*>(g_w_t) + (size_t)bu * TILE_BYTES
              + swz((uint32_t)(rr * 128 + cu * 16));
    *reinterpret_cast<uint4*>(dst) = out;
}

// ---------------- fused GEMM + LSTM epilogue ----------------
// stage load = two linear 16KB copies (images are pre-swizzled)
DEVINL void load_stage(uint32_t sbase, const char* gA, const char* gB, int kt, int tid) {
    const char* srcA = gA + (size_t)kt * TILE_BYTES;
    const char* srcB = gB + (size_t)kt * TILE_BYTES;
    const uint32_t t16 = (uint32_t)tid * 16;
#pragma unroll
    for (int i = 0; i < 4; i++) {
        const uint32_t off = t16 + (uint32_t)i * 4096;
        cp16(sbase + off, srcA + off);
    }
#pragma unroll
    for (int i = 0; i < 4; i++) {
        const uint32_t off = t16 + (uint32_t)i * 4096;
        cp16(sbase + B_OFF + off, srcB + off);
    }
}

__global__ void __launch_bounds__(THREADS)
lstm_gemm_kernel(const float* __restrict__ c_prev,
                 const float* __restrict__ bxi, const float* __restrict__ bhi,
                 const float* __restrict__ bxf, const float* __restrict__ bhf,
                 const float* __restrict__ bxc, const float* __restrict__ bhc,
                 const float* __restrict__ bxo, const float* __restrict__ bho,
                 float* __restrict__ outH, float* __restrict__ outC) {
    extern __shared__ char smraw[];
    const uint32_t raw  = smem_u32(smraw);
    const uint32_t base = (raw + 1023u) & ~1023u;

    const int tid  = threadIdx.x;
    const int lane = tid & 31;
    const int wid  = tid >> 5;
    const int wm   = wid >> 2;           // 0..1 : 64-row slice
    const int wn   = wid & 3;            // 0..3 : 8-col slice (per gate)
    const int m0   = blockIdx.x * BM;
    const int n0   = blockIdx.y * BNG;

    const char* gA = reinterpret_cast<const char*>(g_xh_t)
                   + (size_t)blockIdx.x * KITERS * TILE_BYTES;
    const char* gB = reinterpret_cast<const char*>(g_w_t)
                   + (size_t)blockIdx.y * KITERS * TILE_BYTES;

    float acc[4][4][4];                  // [mtile][gate][reg]
#pragma unroll
    for (int t = 0; t < 4; t++)
#pragma unroll
        for (int g = 0; g < 4; g++)
#pragma unroll
            for (int r = 0; r < 4; r++) acc[t][g][r] = 0.0f;

    // prologue: stages 0,1
    load_stage(base + 0 * STAGE_BYTES, gA, gB, 0, tid);
    cp_commit();
    load_stage(base + 1 * STAGE_BYTES, gA, gB, 1, tid);
    cp_commit();

    const uint32_t aRowOff  = (uint32_t)((wm * 64 + (lane & 15)) * 128 + (lane >> 4) * 16);
    const uint32_t bRowLane = (uint32_t)(wn * 8 + (lane & 7));
    const uint32_t bKOff    = (uint32_t)(((lane >> 3) & 1) * 16);
    const uint32_t bGateSel = (uint32_t)(lane >> 4);   // 0/1 within gate pair

    for (int kt = 0; kt < KITERS; kt++) {
        if (kt == KITERS - 1) cp_wait0(); else cp_wait1();
        __syncthreads();

        const uint32_t sA = base + (uint32_t)(kt % STAGES) * STAGE_BYTES;
        const uint32_t sB = sA + B_OFF;

#pragma unroll
        for (int kk = 0; kk < 4; kk++) {
            uint32_t a[4][4];
#pragma unroll
            for (int t = 0; t < 4; t++) {
                uint32_t addr = sA + swz(aRowOff + (uint32_t)(t * 16 * 128) + (uint32_t)(kk * 32));
                ldsm_x4(a[t][0], a[t][1], a[t][2], a[t][3], addr);
            }
            uint32_t b[4][2];
#pragma unroll
            for (int jp = 0; jp < 2; jp++) {
                uint32_t gate = (uint32_t)jp * 2 + bGateSel;
                uint32_t addr = sB + swz((gate * 32 + bRowLane) * 128 + (uint32_t)(kk * 32) + bKOff);
                ldsm_x4(b[jp * 2][0], b[jp * 2][1], b[jp * 2 + 1][0], b[jp * 2 + 1][1], addr);
            }
#pragma unroll
            for (int t = 0; t < 4; t++)
#pragma unroll
                for (int g = 0; g < 4; g++)
                    mma16816(acc[t][g], a[t], b[g]);
        }

        if (kt + 2 < KITERS) {
            load_stage(base + (uint32_t)((kt + 2) % STAGES) * STAGE_BYTES, gA, gB, kt + 2, tid);
            cp_commit();
        }
    }

    // ---------------- epilogue (register-local gate combine) ----------------
    const int cloc = wn * 8 + 2 * (lane & 3);
    const int c    = n0 + cloc;

    const float bi0 = bxi[c] + bhi[c],     bi1 = bxi[c + 1] + bhi[c + 1];
    const float bf0 = bxf[c] + bhf[c],     bf1 = bxf[c + 1] + bhf[c + 1];
    const float bc0 = bxc[c] + bhc[c],     bc1 = bxc[c + 1] + bhc[c + 1];
    const float bo0 = bxo[c] + bho[c],     bo1 = bxo[c + 1] + bho[c + 1];

#pragma unroll
    for (int t = 0; t < 4; t++) {
        const int r0 = m0 + wm * 64 + t * 16 + (lane >> 2);
#pragma unroll
        for (int h = 0; h < 2; h++) {
            const int row = r0 + 8 * h;
            const float2 cp = *reinterpret_cast<const float2*>(c_prev + (size_t)row * H_DIM + c);

            const float zi0 = acc[t][0][2 * h + 0] + bi0, zi1 = acc[t][0][2 * h + 1] + bi1;
            const float zf0 = acc[t][1][2 * h + 0] + bf0, zf1 = acc[t][1][2 * h + 1] + bf1;
            const float zc0 = acc[t][2][2 * h + 0] + bc0, zc1 = acc[t][2][2 * h + 1] + bc1;
            const float zo0 = acc[t][3][2 * h + 0] + bo0, zo1 = acc[t][3][2 * h + 1] + bo1;

            const float cn0 = sigmoidf_(zf0) * cp.x + sigmoidf_(zi0) * tanhf_(zc0);
            const float cn1 = sigmoidf_(zf1) * cp.y + sigmoidf_(zi1) * tanhf_(zc1);
            const float hn0 = sigmoidf_(zo0) * tanhf_(cn0);
            const float hn1 = sigmoidf_(zo1) * tanhf_(cn1);

            const size_t go = (size_t)row * H_DIM + c;
            *reinterpret_cast<float2*>(outC + go) = make_float2(cn0, cn1);
            *reinterpret_cast<float2*>(outH + go) = make_float2(hn0, hn1);
        }
    }
}

// ---------------- launch ----------------
extern "C" void kernel_launch(void* const* d_in, const int* in_sizes, int n_in,
                              void* d_out, int out_size) {
    (void)in_sizes; (void)n_in; (void)out_size;
    const float* x      = (const float*)d_in[0];
    const float* h_prev = (const float*)d_in[1];
    const float* c_prev = (const float*)d_in[2];
    const float* Wxi = (const float*)d_in[3];
    const float* Whi = (const float*)d_in[4];
    const float* Wxf = (const float*)d_in[5];
    const float* Whf = (const float*)d_in[6];
    const float* Wxc = (const float*)d_in[7];
    const float* Whc = (const float*)d_in[8];
    const float* Wxo = (const float*)d_in[9];
    const float* Who = (const float*)d_in[10];
    const float* bxi = (const float*)d_in[11];
    const float* bhi = (const float*)d_in[12];
    const float* bxf = (const float*)d_in[13];
    const float* bhf = (const float*)d_in[14];
    const float* bxc = (const float*)d_in[15];
    const float* bhc = (const float*)d_in[16];
    const float* bxo = (const float*)d_in[17];
    const float* bho = (const float*)d_in[18];

    float* outH = (float*)d_out;
    float* outC = outH + (size_t)B_DIM * H_DIM;

    // conversions into pre-tiled swizzled fp16 scratch
    cvt_xh_kernel<<<NMBLK * KITERS * 1024 / 256, 256>>>(x, h_prev);
    cvt_w_kernel<<<NNBLK * KITERS * 1024 / 256, 256>>>(Wxi, Whi, Wxf, Whf,
                                                       Wxc, Whc, Wxo, Who);

    // fused GEMM + epilogue
    cudaFuncSetAttribute(lstm_gemm_kernel,
                         cudaFuncAttributeMaxDynamicSharedMemorySize, SMEM_BYTES);
    dim3 grid(NMBLK, NNBLK, 1);   // (64, 32)
    lstm_gemm_kernel<<<grid, THREADS, SMEM_BYTES>>>(
        c_prev, bxi, bhi, bxf, bhf, bxc, bhc, bxo, bho, outH, outC);
}